// round 13
// baseline (speedup 1.0000x reference)
#include <cuda_runtime.h>
#include <cuda_bf16.h>
#include <math.h>
#include <stdint.h>

// Problem dims
#define Bb 4
#define Tt 16
#define Ss 256
#define Dd 512
#define Nn 8
#define Ecols (Dd*Nn)     // 4096
#define Mrows (Bb*Ss)     // 1024
#define Kdim  Dd          // 512
#define KAUG  (3*Kdim)    // 1536 : [hi|hi|lo] x [hi|lo|hi] 3-product split GEMM

typedef unsigned long long ull;

// ---------------- scratch (no allocation allowed -> __device__ globals) ----
__device__ __align__(16) float g_pop[Mrows * Ecols];  // sigmoid(pop response) [m,e] (16.8 MB)
__device__ __align__(16) float g_rate[Bb*Ss*Dd];
__device__ __align__(16) float g_phase[Bb*Ss*Dd];
__device__ __align__(16) int   g_st[Bb*Ss*Dd];
__device__ float g_w[4];
// split-bf16 augmented operands
__device__ __align__(16) __nv_bfloat16 g_xa[Mrows * KAUG];   // 3 MB
__device__ __align__(16) __nv_bfloat16 g_wa[Ecols * KAUG];   // 12.6 MB

// ---------------- helpers ----------------
__device__ __forceinline__ float sigf(float x) {
    if (x >= 0.0f) { return 1.0f / (1.0f + expf(-x)); }
    float z = expf(x);
    return z / (1.0f + z);
}

__device__ __forceinline__ uint32_t smem_u32(const void* p) {
    uint32_t a;
    asm("{ .reg .u64 t; cvta.to.shared.u64 t, %1; cvt.u32.u64 %0, t; }" : "=r"(a) : "l"(p));
    return a;
}

__device__ __forceinline__ void cp16(uint32_t s, const void* g) {
    asm volatile("cp.async.cg.shared.global [%0], [%1], 16;" :: "r"(s), "l"(g) : "memory");
}

#define LDSM4(r, addr) \
    asm volatile("ldmatrix.sync.aligned.m8n8.x4.shared.b16 {%0,%1,%2,%3}, [%4];" \
        : "=r"((r)[0]), "=r"((r)[1]), "=r"((r)[2]), "=r"((r)[3]) : "r"(addr))

#define MMA16816(d, a, b0, b1) \
    asm volatile("mma.sync.aligned.m16n8k16.row.col.f32.bf16.bf16.f32 " \
        "{%0,%1,%2,%3}, {%4,%5,%6,%7}, {%8,%9}, {%0,%1,%2,%3};" \
        : "+f"((d)[0]), "+f"((d)[1]), "+f"((d)[2]), "+f"((d)[3]) \
        : "r"((a)[0]), "r"((a)[1]), "r"((a)[2]), "r"((a)[3]), "r"(b0), "r"(b1))

__device__ __forceinline__ ull pack4_hi(float4 v, float4& lo) {
    __nv_bfloat16 h0 = __float2bfloat16_rn(v.x);
    __nv_bfloat16 h1 = __float2bfloat16_rn(v.y);
    __nv_bfloat16 h2 = __float2bfloat16_rn(v.z);
    __nv_bfloat16 h3 = __float2bfloat16_rn(v.w);
    lo.x = v.x - __bfloat162float(h0);
    lo.y = v.y - __bfloat162float(h1);
    lo.z = v.z - __bfloat162float(h2);
    lo.w = v.w - __bfloat162float(h3);
    __nv_bfloat162 p0; p0.x = h0; p0.y = h1;
    __nv_bfloat162 p1; p1.x = h2; p1.y = h3;
    uint32_t u0 = *(uint32_t*)&p0, u1 = *(uint32_t*)&p1;
    return (ull)u0 | ((ull)u1 << 32);
}
__device__ __forceinline__ ull pack4(float4 v) {
    __nv_bfloat162 p0; p0.x = __float2bfloat16_rn(v.x); p0.y = __float2bfloat16_rn(v.y);
    __nv_bfloat162 p1; p1.x = __float2bfloat16_rn(v.z); p1.y = __float2bfloat16_rn(v.w);
    uint32_t u0 = *(uint32_t*)&p0, u1 = *(uint32_t*)&p1;
    return (ull)u0 | ((ull)u1 << 32);
}

// ---------------- kernel 1: prep (vectorized x4) + split_x + softmax ------
// One float4 of x per thread: rate/st/phase AND the Xaug bf16 split.
__global__ __launch_bounds__(256) void prep_kernel(
    const float* __restrict__ x,
    const float* __restrict__ noise,
    const float* __restrict__ ew)
{
    int i = blockIdx.x * blockDim.x + threadIdx.x;     // quad id, 131072 total
    float4 xv = *(const float4*)&x[i * 4];
    float4 nv = *(const float4*)&noise[i * 4];

    float s0 = sigf(xv.x), s1 = sigf(xv.y), s2 = sigf(xv.z), s3 = sigf(xv.w);

    float4 rv;
    rv.x = fminf(fmaxf(s0 * 0.9f + 0.05f + nv.x * 0.1f, 0.0f), 1.0f);
    rv.y = fminf(fmaxf(s1 * 0.9f + 0.05f + nv.y * 0.1f, 0.0f), 1.0f);
    rv.z = fminf(fmaxf(s2 * 0.9f + 0.05f + nv.z * 0.1f, 0.0f), 1.0f);
    rv.w = fminf(fmaxf(s3 * 0.9f + 0.05f + nv.w * 0.1f, 0.0f), 1.0f);
    *(float4*)&g_rate[i * 4] = rv;

    int4 st;
    st.x = (int)(s0 * 15.0f); st.y = (int)(s1 * 15.0f);
    st.z = (int)(s2 * 15.0f); st.w = (int)(s3 * 15.0f);
    *(int4*)&g_st[i * 4] = st;

    float4 ph;
    ph.x = s0 * 6.2831855f; ph.y = s1 * 6.2831855f;
    ph.z = s2 * 6.2831855f; ph.w = s3 * 6.2831855f;
    *(float4*)&g_phase[i * 4] = ph;

    // Xaug split: row m = (i*4)/512, q = ull index within 128-ull segment
    int m = i >> 7, q = i & 127;
    float4 lo; ull hi = pack4_hi(xv, lo); ull lp = pack4(lo);
    ull* row = (ull*)&g_xa[(size_t)m * KAUG];
    row[q] = hi; row[128 + q] = hi; row[256 + q] = lp;

    if (i == 0) {
        float m2 = fmaxf(fmaxf(ew[0], ew[1]), fmaxf(ew[2], ew[3]));
        float e0 = expf(ew[0]-m2), e1 = expf(ew[1]-m2), e2 = expf(ew[2]-m2), e3 = expf(ew[3]-m2);
        float s = e0 + e1 + e2 + e3;
        g_w[0] = e0/s; g_w[1] = e1/s; g_w[2] = e2/s; g_w[3] = e3/s;
    }
}

// ---------------- kernel 1b: split W -> bf16 hi/lo augmented --------------
// Waug row: [Whi | Wlo | Whi]
__global__ __launch_bounds__(256) void split_w_kernel(const float* __restrict__ W)
{
    int i = blockIdx.x * blockDim.x + threadIdx.x;     // quad id, 4096*128
    int n = i >> 7, q = i & 127;
    float4 v = *(const float4*)&W[n * Kdim + (q << 2)];
    float4 lo; ull hi = pack4_hi(v, lo); ull lp = pack4(lo);
    ull* row = (ull*)&g_wa[(size_t)n * KAUG];
    row[q] = hi; row[128 + q] = lp; row[256 + q] = hi;
}

// ---------------- kernel 2: bf16 mma.sync GEMM, fused sigmoid epilogue ----
// g_pop[m,e] = sigmoid( Xaug[m,:] . Waug[e,:] + bias[e] ),  K' = 1536
// 128 threads, 4 warps 2x2, warp tile 64x64: per kk-step 8 LDSM -> 32 MMA
// (4:1 density). BK=64, 2-stage, one sync/iter, prefetch-after-sync.
// ~185 regs -> 2 CTAs/SM; smem 73.7KB -> 2 CTAs; 256 CTAs = one wave.
#define BM 128
#define BN 128
#define BK2 64
#define NKT2 (KAUG/BK2)      // 24
#define TSTR2 144            // 128B data + 16B pad: conflict-free ldmatrix
#define ATILE2 (128*TSTR2)   // 18432 B per tile
#define STAGE2 (2*ATILE2)    // A+B per stage = 36864 B
#define SMEM_GEMM (2*STAGE2) // 73728 B

__global__ __launch_bounds__(128, 2) void gemm_mma_kernel(const float* __restrict__ bias)
{
    extern __shared__ __align__(16) char sm_dyn[];
    const uint32_t sbase = smem_u32(sm_dyn);
    const int tid = threadIdx.x;
    const int w = tid >> 5, l = tid & 31;
    const int wm = w >> 1, wn = w & 1;             // 2x2 warp grid, warp tile 64x64
    const int m0 = blockIdx.y * BM, n0 = blockIdx.x * BN;

    float acc[4][8][4];
    #pragma unroll
    for (int mt = 0; mt < 4; mt++)
        #pragma unroll
        for (int nt = 0; nt < 8; nt++)
            #pragma unroll
            for (int j = 0; j < 4; j++) acc[mt][nt][j] = 0.0f;

    // hoisted ldmatrix base offsets (per-warp constant)
    const int lr = l & 15, lh = l >> 4;
    uint32_t aoff[4], boff[4];
    #pragma unroll
    for (int mt = 0; mt < 4; mt++) aoff[mt] = (uint32_t)((wm*64 + mt*16 + lr) * TSTR2 + lh*16);
    #pragma unroll
    for (int np = 0; np < 4; np++) boff[np] = (uint32_t)((wn*64 + np*16 + lr) * TSTR2 + lh*16);

    // loader: each of 128 threads owns one tile row (128 B = 8 x 16B chunks)
    const char* gA = (const char*)g_xa + (size_t)(m0 + tid) * KAUG * 2;
    const char* gB = (const char*)g_wa + (size_t)(n0 + tid) * KAUG * 2;
    const uint32_t so = (uint32_t)(tid * TSTR2);

    auto load_stage = [&](int buf) {
        const uint32_t sA = sbase + (uint32_t)(buf * STAGE2) + so;
        const uint32_t sB = sA + ATILE2;
        #pragma unroll
        for (int j = 0; j < 8; j++) {
            cp16(sA + j * 16u, gA + j * 16);
            cp16(sB + j * 16u, gB + j * 16);
        }
        asm volatile("cp.async.commit_group;" ::: "memory");
        gA += 128;  // advance one BK2 stage (64 bf16)
        gB += 128;
    };

    load_stage(0);

    for (int kt = 0; kt < NKT2; kt++) {
        const int buf = kt & 1;
        asm volatile("cp.async.wait_group 0;" ::: "memory");
        __syncthreads();   // stage kt visible; all warps done computing kt-1
        if (kt + 1 < NKT2) load_stage(buf ^ 1);   // overlaps compute below

        const uint32_t sA = sbase + (uint32_t)(buf * STAGE2);
        const uint32_t sB = sA + ATILE2;
        #pragma unroll
        for (int kk = 0; kk < 4; kk++) {           // four k16 steps per BK=64
            uint32_t a[4][4], b[4][4];
            #pragma unroll
            for (int mt = 0; mt < 4; mt++) LDSM4(a[mt], sA + aoff[mt] + kk*32);
            #pragma unroll
            for (int np = 0; np < 4; np++) LDSM4(b[np], sB + boff[np] + kk*32);
            #pragma unroll
            for (int mt = 0; mt < 4; mt++)
                #pragma unroll
                for (int np = 0; np < 4; np++) {
                    MMA16816(acc[mt][np*2],     a[mt], b[np][0], b[np][2]);
                    MMA16816(acc[mt][np*2 + 1], a[mt], b[np][1], b[np][3]);
                }
        }
    }

    // epilogue: bias + stable sigmoid, write g_pop
    #pragma unroll
    for (int mt = 0; mt < 4; mt++) {
        int row = m0 + wm*64 + mt*16 + (l >> 2);
        #pragma unroll
        for (int nt = 0; nt < 8; nt++) {
            int col = n0 + wn*64 + nt*8 + 2*(l & 3);
            float2 bb = *(const float2*)&bias[col];
            float2 o0, o1;
            o0.x = sigf(acc[mt][nt][0] + bb.x);
            o0.y = sigf(acc[mt][nt][1] + bb.y);
            o1.x = sigf(acc[mt][nt][2] + bb.x);
            o1.y = sigf(acc[mt][nt][3] + bb.y);
            *(float2*)&g_pop[(size_t)row * Ecols + col] = o0;
            *(float2*)&g_pop[(size_t)(row + 8) * Ecols + col] = o1;
        }
    }
}

// ---------------- kernel 3: fused streaming combine (t-paired) ------------
__global__ __launch_bounds__(256) void fuse_kernel(
    const float* __restrict__ freq,
    const float* __restrict__ rrate,
    const float* __restrict__ rpop,
    float* __restrict__ out)
{
    int idx = blockIdx.x * blockDim.x + threadIdx.x;   // [B, 8, S, D] linear
    int d  = idx & (Dd - 1);
    int s  = (idx >> 9) & (Ss - 1);
    int th = (idx >> 17) & 7;        // t half: handles t=th and t=th+8
    int b  = idx >> 20;
    int bsd = (b * Ss + s) * Dd + d;
    int i0 = ((b * Tt + th) * Ss + s) * Dd + d;
    int i1 = i0 + 8 * Ss * Dd;

    float w0 = g_w[0], w1 = g_w[1], w2 = g_w[2], w3 = g_w[3];

    float rate  = g_rate[bsd];
    int   st    = g_st[bsd];
    float phase = g_phase[bsd];
    float fd    = freq[d];

    const float4* pr4 = (const float4*)g_pop + (size_t)bsd * 2;
    float4 p0 = pr4[0], p1 = pr4[1];

    const float4* ra = (const float4*)rpop + (size_t)i0 * 2;
    const float4* rb = (const float4*)rpop + (size_t)i1 * 2;
    float4 a0 = ra[0], a1 = ra[1];
    float4 b0 = rb[0], b1 = rb[1];
    float rr0 = rrate[i0], rr1 = rrate[i1];

    int cnt0 = (a0.x < p0.x) + (a0.y < p0.y) + (a0.z < p0.z) + (a0.w < p0.w)
             + (a1.x < p1.x) + (a1.y < p1.y) + (a1.z < p1.z) + (a1.w < p1.w);
    int cnt1 = (b0.x < p0.x) + (b0.y < p0.y) + (b0.z < p0.z) + (b0.w < p0.w)
             + (b1.x < p1.x) + (b1.y < p1.y) + (b1.z < p1.z) + (b1.w < p1.w);

    const float tstep = 6.2831855f / 15.0f;
    float wv0 = sinf(fd * ((float)th * tstep) + phase);
    float wv1 = sinf(fd * ((float)(th + 8) * tstep) + phase);

    float o0 = w0 * ((rr0 < rate) ? 1.0f : 0.0f)
             + w1 * ((th == st) ? 1.0f : 0.0f)
             + w2 * ((float)cnt0 * 0.125f)
             + w3 * ((wv0 > 0.5f) ? 1.0f : 0.0f);
    float o1 = w0 * ((rr1 < rate) ? 1.0f : 0.0f)
             + w1 * ((th + 8 == st) ? 1.0f : 0.0f)
             + w2 * ((float)cnt1 * 0.125f)
             + w3 * ((wv1 > 0.5f) ? 1.0f : 0.0f);

    out[i0] = o0;
    out[i1] = o1;
}

// ---------------- launch ---------------------------------------------------
extern "C" void kernel_launch(void* const* d_in, const int* in_sizes, int n_in,
                              void* d_out, int out_size)
{
    const float* x     = (const float*)d_in[0];  // [B,S,D]
    const float* freq  = (const float*)d_in[1];  // [D]
    const float* pw    = (const float*)d_in[2];  // [D*N, D]
    const float* pb    = (const float*)d_in[3];  // [D*N]
    const float* ew    = (const float*)d_in[4];  // [4]
    const float* noise = (const float*)d_in[5];  // [B,S,D]
    const float* rr    = (const float*)d_in[6];  // [B,T,S,D]
    const float* rp    = (const float*)d_in[7];  // [B,T,S,D,N]
    float* out = (float*)d_out;                  // [B,T,S,D]

    cudaFuncSetAttribute(gemm_mma_kernel,
                         cudaFuncAttributeMaxDynamicSharedMemorySize, SMEM_GEMM);

    prep_kernel<<<(Bb*Ss*Dd/4) / 256, 256>>>(x, noise, ew);
    split_w_kernel<<<(Ecols*Kdim/4) / 256, 256>>>(pw);
    gemm_mma_kernel<<<dim3(Ecols / BN, Mrows / BM), 128, SMEM_GEMM>>>(pb);
    fuse_kernel<<<(Bb*(Tt/2)*Ss*Dd) / 256, 256>>>(freq, rr, rp, out);
}

// round 14
// speedup vs baseline: 1.3256x; 1.3256x over previous
#include <cuda_runtime.h>
#include <cuda_bf16.h>
#include <math.h>
#include <stdint.h>

// Problem dims
#define Bb 4
#define Tt 16
#define Ss 256
#define Dd 512
#define Nn 8
#define Ecols (Dd*Nn)     // 4096
#define Mrows (Bb*Ss)     // 1024
#define Kdim  Dd          // 512
#define KAUG  (3*Kdim)    // 1536 : [hi|hi|lo] x [hi|lo|hi] 3-product split GEMM

typedef unsigned long long ull;

// ---------------- scratch (no allocation allowed -> __device__ globals) ----
__device__ __align__(16) float g_pop[Mrows * Ecols];  // sigmoid(pop response) [m,e] (16.8 MB)
__device__ __align__(16) float g_rate[Bb*Ss*Dd];
__device__ __align__(16) float g_phase[Bb*Ss*Dd];
__device__ __align__(16) int   g_st[Bb*Ss*Dd];
__device__ float g_w[4];
// split-bf16 augmented operands
__device__ __align__(16) __nv_bfloat16 g_xa[Mrows * KAUG];   // 3 MB
__device__ __align__(16) __nv_bfloat16 g_wa[Ecols * KAUG];   // 12.6 MB

// ---------------- helpers ----------------
__device__ __forceinline__ float sigf(float x) {
    if (x >= 0.0f) { return 1.0f / (1.0f + expf(-x)); }
    float z = expf(x);
    return z / (1.0f + z);
}

__device__ __forceinline__ uint32_t smem_u32(const void* p) {
    uint32_t a;
    asm("{ .reg .u64 t; cvta.to.shared.u64 t, %1; cvt.u32.u64 %0, t; }" : "=r"(a) : "l"(p));
    return a;
}

__device__ __forceinline__ void cp16(uint32_t s, const void* g) {
    asm volatile("cp.async.cg.shared.global [%0], [%1], 16;" :: "r"(s), "l"(g) : "memory");
}

#define LDSM4(r, addr) \
    asm volatile("ldmatrix.sync.aligned.m8n8.x4.shared.b16 {%0,%1,%2,%3}, [%4];" \
        : "=r"((r)[0]), "=r"((r)[1]), "=r"((r)[2]), "=r"((r)[3]) : "r"(addr))

#define MMA16816(d, a, b0, b1) \
    asm volatile("mma.sync.aligned.m16n8k16.row.col.f32.bf16.bf16.f32 " \
        "{%0,%1,%2,%3}, {%4,%5,%6,%7}, {%8,%9}, {%0,%1,%2,%3};" \
        : "+f"((d)[0]), "+f"((d)[1]), "+f"((d)[2]), "+f"((d)[3]) \
        : "r"((a)[0]), "r"((a)[1]), "r"((a)[2]), "r"((a)[3]), "r"(b0), "r"(b1))

__device__ __forceinline__ ull pack4_hi(float4 v, float4& lo) {
    __nv_bfloat16 h0 = __float2bfloat16_rn(v.x);
    __nv_bfloat16 h1 = __float2bfloat16_rn(v.y);
    __nv_bfloat16 h2 = __float2bfloat16_rn(v.z);
    __nv_bfloat16 h3 = __float2bfloat16_rn(v.w);
    lo.x = v.x - __bfloat162float(h0);
    lo.y = v.y - __bfloat162float(h1);
    lo.z = v.z - __bfloat162float(h2);
    lo.w = v.w - __bfloat162float(h3);
    __nv_bfloat162 p0; p0.x = h0; p0.y = h1;
    __nv_bfloat162 p1; p1.x = h2; p1.y = h3;
    uint32_t u0 = *(uint32_t*)&p0, u1 = *(uint32_t*)&p1;
    return (ull)u0 | ((ull)u1 << 32);
}
__device__ __forceinline__ ull pack4(float4 v) {
    __nv_bfloat162 p0; p0.x = __float2bfloat16_rn(v.x); p0.y = __float2bfloat16_rn(v.y);
    __nv_bfloat162 p1; p1.x = __float2bfloat16_rn(v.z); p1.y = __float2bfloat16_rn(v.w);
    uint32_t u0 = *(uint32_t*)&p0, u1 = *(uint32_t*)&p1;
    return (ull)u0 | ((ull)u1 << 32);
}

// ---------------- kernel 1: prep (vectorized x4) + split_x + softmax ------
__global__ __launch_bounds__(256) void prep_kernel(
    const float* __restrict__ x,
    const float* __restrict__ noise,
    const float* __restrict__ ew)
{
    int i = blockIdx.x * blockDim.x + threadIdx.x;     // quad id, 131072 total
    float4 xv = *(const float4*)&x[i * 4];
    float4 nv = *(const float4*)&noise[i * 4];

    float s0 = sigf(xv.x), s1 = sigf(xv.y), s2 = sigf(xv.z), s3 = sigf(xv.w);

    float4 rv;
    rv.x = fminf(fmaxf(s0 * 0.9f + 0.05f + nv.x * 0.1f, 0.0f), 1.0f);
    rv.y = fminf(fmaxf(s1 * 0.9f + 0.05f + nv.y * 0.1f, 0.0f), 1.0f);
    rv.z = fminf(fmaxf(s2 * 0.9f + 0.05f + nv.z * 0.1f, 0.0f), 1.0f);
    rv.w = fminf(fmaxf(s3 * 0.9f + 0.05f + nv.w * 0.1f, 0.0f), 1.0f);
    *(float4*)&g_rate[i * 4] = rv;

    int4 st;
    st.x = (int)(s0 * 15.0f); st.y = (int)(s1 * 15.0f);
    st.z = (int)(s2 * 15.0f); st.w = (int)(s3 * 15.0f);
    *(int4*)&g_st[i * 4] = st;

    float4 ph;
    ph.x = s0 * 6.2831855f; ph.y = s1 * 6.2831855f;
    ph.z = s2 * 6.2831855f; ph.w = s3 * 6.2831855f;
    *(float4*)&g_phase[i * 4] = ph;

    // Xaug split: row m = (i*4)/512
    int m = i >> 7, q = i & 127;
    float4 lo; ull hi = pack4_hi(xv, lo); ull lp = pack4(lo);
    ull* row = (ull*)&g_xa[(size_t)m * KAUG];
    row[q] = hi; row[128 + q] = hi; row[256 + q] = lp;

    if (i == 0) {
        float m2 = fmaxf(fmaxf(ew[0], ew[1]), fmaxf(ew[2], ew[3]));
        float e0 = expf(ew[0]-m2), e1 = expf(ew[1]-m2), e2 = expf(ew[2]-m2), e3 = expf(ew[3]-m2);
        float s = e0 + e1 + e2 + e3;
        g_w[0] = e0/s; g_w[1] = e1/s; g_w[2] = e2/s; g_w[3] = e3/s;
    }
}

// ---------------- kernel 1b: split W -> bf16 hi/lo augmented --------------
__global__ __launch_bounds__(256) void split_w_kernel(const float* __restrict__ W)
{
    int i = blockIdx.x * blockDim.x + threadIdx.x;     // quad id, 4096*128
    int n = i >> 7, q = i & 127;
    float4 v = *(const float4*)&W[n * Kdim + (q << 2)];
    float4 lo; ull hi = pack4_hi(v, lo); ull lp = pack4(lo);
    ull* row = (ull*)&g_wa[(size_t)n * KAUG];
    row[q] = hi; row[128 + q] = lp; row[256 + q] = hi;
}

// ---------------- kernel 2: bf16 mma.sync GEMM (R12 config, 63.0us) -------
// 256 threads, 8 warps 4x2 (warp tile 32x64), BK=64, 3-stage cp.async,
// incremental global pointers, one __syncthreads per iteration, 2 CTAs/SM.
#define BM 128
#define BN 128
#define BK2 64
#define NKT2 (KAUG/BK2)      // 24
#define TSTR2 144            // 128B data + 16B pad: conflict-free ldmatrix
#define ATILE2 (128*TSTR2)   // 18432 B per tile
#define STAGE2 (2*ATILE2)    // A+B per stage = 36864 B
#define SMEM_GEMM (3*STAGE2) // 110592 B

__global__ __launch_bounds__(256, 2) void gemm_mma_kernel(const float* __restrict__ bias)
{
    extern __shared__ __align__(16) char sm_dyn[];
    const uint32_t sbase = smem_u32(sm_dyn);
    const int tid = threadIdx.x;
    const int w = tid >> 5, l = tid & 31;
    const int wm = w & 3, wn = w >> 2;             // 4x2 warp grid, warp tile 32x64
    const int m0 = blockIdx.y * BM, n0 = blockIdx.x * BN;

    float acc[2][8][4];
    #pragma unroll
    for (int mt = 0; mt < 2; mt++)
        #pragma unroll
        for (int nt = 0; nt < 8; nt++)
            #pragma unroll
            for (int j = 0; j < 4; j++) acc[mt][nt][j] = 0.0f;

    const int lr = l & 15, lh = l >> 4;
    uint32_t aoff[2], boff[4];
    #pragma unroll
    for (int mt = 0; mt < 2; mt++) aoff[mt] = (uint32_t)((wm*32 + mt*16 + lr) * TSTR2 + lh*16);
    #pragma unroll
    for (int np = 0; np < 4; np++) boff[np] = (uint32_t)((wn*64 + np*16 + lr) * TSTR2 + lh*16);

    // incremental global pointers: thread's chunk = row (tid>>3), kc (tid&7)
    const int trow = tid >> 3, tkc = tid & 7;
    const char* gA = (const char*)g_xa + ((size_t)(m0 + trow) * KAUG + tkc * 8) * 2;
    const char* gB = (const char*)g_wa + ((size_t)(n0 + trow) * KAUG + tkc * 8) * 2;
    const uint32_t so = (uint32_t)(trow * TSTR2 + tkc * 16);

    auto load_stage = [&](int buf) {
        const uint32_t sA = sbase + (uint32_t)(buf * STAGE2) + so;
        const uint32_t sB = sA + ATILE2;
        #pragma unroll
        for (int j = 0; j < 4; j++) {
            cp16(sA + j * 4608u, gA + j * 98304);
            cp16(sB + j * 4608u, gB + j * 98304);
        }
        asm volatile("cp.async.commit_group;" ::: "memory");
        gA += 128;  // advance one BK2 stage (64 bf16)
        gB += 128;
    };

    load_stage(0);
    load_stage(1);

    int buf = 0, lb = 2;
    for (int kt = 0; kt < NKT2; kt++) {
        if (kt < NKT2 - 1) {
            asm volatile("cp.async.wait_group 1;" ::: "memory");
        } else {
            asm volatile("cp.async.wait_group 0;" ::: "memory");
        }
        __syncthreads();
        if (kt + 2 < NKT2) {
            load_stage(lb);
            lb = (lb == 2) ? 0 : lb + 1;
        }

        const uint32_t sA = sbase + (uint32_t)(buf * STAGE2);
        const uint32_t sB = sA + ATILE2;
        #pragma unroll
        for (int kk = 0; kk < 4; kk++) {
            uint32_t a[2][4], b[4][4];
            #pragma unroll
            for (int mt = 0; mt < 2; mt++) LDSM4(a[mt], sA + aoff[mt] + kk*32);
            #pragma unroll
            for (int np = 0; np < 4; np++) LDSM4(b[np], sB + boff[np] + kk*32);
            #pragma unroll
            for (int mt = 0; mt < 2; mt++)
                #pragma unroll
                for (int np = 0; np < 4; np++) {
                    MMA16816(acc[mt][np*2],     a[mt], b[np][0], b[np][2]);
                    MMA16816(acc[mt][np*2 + 1], a[mt], b[np][1], b[np][3]);
                }
        }
        buf = (buf == 2) ? 0 : buf + 1;
    }

    // epilogue: bias + stable sigmoid, write g_pop
    #pragma unroll
    for (int mt = 0; mt < 2; mt++) {
        int row = m0 + wm*32 + mt*16 + (l >> 2);
        #pragma unroll
        for (int nt = 0; nt < 8; nt++) {
            int col = n0 + wn*64 + nt*8 + 2*(l & 3);
            float2 bb = *(const float2*)&bias[col];
            float2 o0, o1;
            o0.x = sigf(acc[mt][nt][0] + bb.x);
            o0.y = sigf(acc[mt][nt][1] + bb.y);
            o1.x = sigf(acc[mt][nt][2] + bb.x);
            o1.y = sigf(acc[mt][nt][3] + bb.y);
            *(float2*)&g_pop[(size_t)row * Ecols + col] = o0;
            *(float2*)&g_pop[(size_t)(row + 8) * Ecols + col] = o1;
        }
    }
}

// ---------------- kernel 3: fused streaming combine (t-quad) --------------
// Each thread handles t in {th, th+4, th+8, th+12} for one (b,s,d):
// quarters g_pop/scalar reads, 8 in-flight float4 loads on rand_pop stream.
__global__ __launch_bounds__(256) void fuse_kernel(
    const float* __restrict__ freq,
    const float* __restrict__ rrate,
    const float* __restrict__ rpop,
    float* __restrict__ out)
{
    int idx = blockIdx.x * blockDim.x + threadIdx.x;   // [B, 4, S, D] linear
    int d  = idx & (Dd - 1);
    int s  = (idx >> 9) & (Ss - 1);
    int th = (idx >> 17) & 3;        // t quarter: t = th + 4*j
    int b  = idx >> 19;
    int bsd = (b * Ss + s) * Dd + d;
    int i0 = ((b * Tt + th) * Ss + s) * Dd + d;
    const int TS = 4 * Ss * Dd;      // t-step of 4 in elements

    float w0 = g_w[0], w1 = g_w[1], w2 = g_w[2], w3 = g_w[3];

    float rate  = g_rate[bsd];
    int   st    = g_st[bsd];
    float phase = g_phase[bsd];
    float fd    = freq[d];

    const float4* pr4 = (const float4*)g_pop + (size_t)bsd * 2;
    float4 p0 = pr4[0], p1 = pr4[1];

    // issue all rand_pop + rand_rate loads up front (MLP)
    float4 q0[4], q1[4];
    float rr[4];
    #pragma unroll
    for (int j = 0; j < 4; j++) {
        const float4* rp4 = (const float4*)rpop + (size_t)(i0 + j * TS) * 2;
        q0[j] = rp4[0];
        q1[j] = rp4[1];
        rr[j] = rrate[i0 + j * TS];
    }

    const float tstep = 6.2831855f / 15.0f;
    #pragma unroll
    for (int j = 0; j < 4; j++) {
        int t = th + 4 * j;
        int cnt = (q0[j].x < p0.x) + (q0[j].y < p0.y) + (q0[j].z < p0.z) + (q0[j].w < p0.w)
                + (q1[j].x < p1.x) + (q1[j].y < p1.y) + (q1[j].z < p1.z) + (q1[j].w < p1.w);
        float wave = sinf(fd * ((float)t * tstep) + phase);
        float o = w0 * ((rr[j] < rate) ? 1.0f : 0.0f)
                + w1 * ((t == st) ? 1.0f : 0.0f)
                + w2 * ((float)cnt * 0.125f)
                + w3 * ((wave > 0.5f) ? 1.0f : 0.0f);
        out[i0 + j * TS] = o;
    }
}

// ---------------- launch ---------------------------------------------------
extern "C" void kernel_launch(void* const* d_in, const int* in_sizes, int n_in,
                              void* d_out, int out_size)
{
    const float* x     = (const float*)d_in[0];  // [B,S,D]
    const float* freq  = (const float*)d_in[1];  // [D]
    const float* pw    = (const float*)d_in[2];  // [D*N, D]
    const float* pb    = (const float*)d_in[3];  // [D*N]
    const float* ew    = (const float*)d_in[4];  // [4]
    const float* noise = (const float*)d_in[5];  // [B,S,D]
    const float* rr    = (const float*)d_in[6];  // [B,T,S,D]
    const float* rp    = (const float*)d_in[7];  // [B,T,S,D,N]
    float* out = (float*)d_out;                  // [B,T,S,D]

    cudaFuncSetAttribute(gemm_mma_kernel,
                         cudaFuncAttributeMaxDynamicSharedMemorySize, SMEM_GEMM);

    prep_kernel<<<(Bb*Ss*Dd/4) / 256, 256>>>(x, noise, ew);
    split_w_kernel<<<(Ecols*Kdim/4) / 256, 256>>>(pw);
    gemm_mma_kernel<<<dim3(Ecols / BN, Mrows / BM), 256, SMEM_GEMM>>>(pb);
    fuse_kernel<<<(Bb*(Tt/4)*Ss*Dd) / 256, 256>>>(freq, rr, rp, out);
}

// round 15
// speedup vs baseline: 1.3334x; 1.0059x over previous
#include <cuda_runtime.h>
#include <cuda_bf16.h>
#include <math.h>
#include <stdint.h>

// Problem dims
#define Bb 4
#define Tt 16
#define Ss 256
#define Dd 512
#define Nn 8
#define Ecols (Dd*Nn)     // 4096
#define Mrows (Bb*Ss)     // 1024
#define Kdim  Dd          // 512
#define KAUG  (3*Kdim)    // 1536 : [hi|hi|lo] x [hi|lo|hi] 3-product split GEMM

typedef unsigned long long ull;

// ---------------- scratch (no allocation allowed -> __device__ globals) ----
__device__ __align__(16) float g_pop[Mrows * Ecols];  // sigmoid(pop response) [m,e] (16.8 MB)
__device__ __align__(16) float g_rate[Bb*Ss*Dd];
__device__ __align__(16) float g_phase[Bb*Ss*Dd];
__device__ __align__(16) int   g_st[Bb*Ss*Dd];
__device__ float g_w[4];
// split-bf16 augmented operands
__device__ __align__(16) __nv_bfloat16 g_xa[Mrows * KAUG];   // 3 MB
__device__ __align__(16) __nv_bfloat16 g_wa[Ecols * KAUG];   // 12.6 MB

// ---------------- helpers ----------------
__device__ __forceinline__ float sigf(float x) {
    if (x >= 0.0f) { return 1.0f / (1.0f + expf(-x)); }
    float z = expf(x);
    return z / (1.0f + z);
}

__device__ __forceinline__ uint32_t smem_u32(const void* p) {
    uint32_t a;
    asm("{ .reg .u64 t; cvta.to.shared.u64 t, %1; cvt.u32.u64 %0, t; }" : "=r"(a) : "l"(p));
    return a;
}

__device__ __forceinline__ void cp16(uint32_t s, const void* g) {
    asm volatile("cp.async.cg.shared.global [%0], [%1], 16;" :: "r"(s), "l"(g) : "memory");
}

#define LDSM4(r, addr) \
    asm volatile("ldmatrix.sync.aligned.m8n8.x4.shared.b16 {%0,%1,%2,%3}, [%4];" \
        : "=r"((r)[0]), "=r"((r)[1]), "=r"((r)[2]), "=r"((r)[3]) : "r"(addr))

#define MMA16816(d, a, b0, b1) \
    asm volatile("mma.sync.aligned.m16n8k16.row.col.f32.bf16.bf16.f32 " \
        "{%0,%1,%2,%3}, {%4,%5,%6,%7}, {%8,%9}, {%0,%1,%2,%3};" \
        : "+f"((d)[0]), "+f"((d)[1]), "+f"((d)[2]), "+f"((d)[3]) \
        : "r"((a)[0]), "r"((a)[1]), "r"((a)[2]), "r"((a)[3]), "r"(b0), "r"(b1))

__device__ __forceinline__ ull pack4_hi(float4 v, float4& lo) {
    __nv_bfloat16 h0 = __float2bfloat16_rn(v.x);
    __nv_bfloat16 h1 = __float2bfloat16_rn(v.y);
    __nv_bfloat16 h2 = __float2bfloat16_rn(v.z);
    __nv_bfloat16 h3 = __float2bfloat16_rn(v.w);
    lo.x = v.x - __bfloat162float(h0);
    lo.y = v.y - __bfloat162float(h1);
    lo.z = v.z - __bfloat162float(h2);
    lo.w = v.w - __bfloat162float(h3);
    __nv_bfloat162 p0; p0.x = h0; p0.y = h1;
    __nv_bfloat162 p1; p1.x = h2; p1.y = h3;
    uint32_t u0 = *(uint32_t*)&p0, u1 = *(uint32_t*)&p1;
    return (ull)u0 | ((ull)u1 << 32);
}
__device__ __forceinline__ ull pack4(float4 v) {
    __nv_bfloat162 p0; p0.x = __float2bfloat16_rn(v.x); p0.y = __float2bfloat16_rn(v.y);
    __nv_bfloat162 p1; p1.x = __float2bfloat16_rn(v.z); p1.y = __float2bfloat16_rn(v.w);
    uint32_t u0 = *(uint32_t*)&p0, u1 = *(uint32_t*)&p1;
    return (ull)u0 | ((ull)u1 << 32);
}

// ---------------- kernel 1: prep (vectorized x4) + split_x + softmax ------
__global__ __launch_bounds__(256) void prep_kernel(
    const float* __restrict__ x,
    const float* __restrict__ noise,
    const float* __restrict__ ew)
{
    int i = blockIdx.x * blockDim.x + threadIdx.x;     // quad id, 131072 total
    float4 xv = *(const float4*)&x[i * 4];
    float4 nv = *(const float4*)&noise[i * 4];

    float s0 = sigf(xv.x), s1 = sigf(xv.y), s2 = sigf(xv.z), s3 = sigf(xv.w);

    float4 rv;
    rv.x = fminf(fmaxf(s0 * 0.9f + 0.05f + nv.x * 0.1f, 0.0f), 1.0f);
    rv.y = fminf(fmaxf(s1 * 0.9f + 0.05f + nv.y * 0.1f, 0.0f), 1.0f);
    rv.z = fminf(fmaxf(s2 * 0.9f + 0.05f + nv.z * 0.1f, 0.0f), 1.0f);
    rv.w = fminf(fmaxf(s3 * 0.9f + 0.05f + nv.w * 0.1f, 0.0f), 1.0f);
    *(float4*)&g_rate[i * 4] = rv;

    int4 st;
    st.x = (int)(s0 * 15.0f); st.y = (int)(s1 * 15.0f);
    st.z = (int)(s2 * 15.0f); st.w = (int)(s3 * 15.0f);
    *(int4*)&g_st[i * 4] = st;

    float4 ph;
    ph.x = s0 * 6.2831855f; ph.y = s1 * 6.2831855f;
    ph.z = s2 * 6.2831855f; ph.w = s3 * 6.2831855f;
    *(float4*)&g_phase[i * 4] = ph;

    // Xaug split: row m = (i*4)/512
    int m = i >> 7, q = i & 127;
    float4 lo; ull hi = pack4_hi(xv, lo); ull lp = pack4(lo);
    ull* row = (ull*)&g_xa[(size_t)m * KAUG];
    row[q] = hi; row[128 + q] = hi; row[256 + q] = lp;

    if (i == 0) {
        float m2 = fmaxf(fmaxf(ew[0], ew[1]), fmaxf(ew[2], ew[3]));
        float e0 = expf(ew[0]-m2), e1 = expf(ew[1]-m2), e2 = expf(ew[2]-m2), e3 = expf(ew[3]-m2);
        float s = e0 + e1 + e2 + e3;
        g_w[0] = e0/s; g_w[1] = e1/s; g_w[2] = e2/s; g_w[3] = e3/s;
    }
}

// ---------------- kernel 1b: split W -> bf16 hi/lo augmented --------------
__global__ __launch_bounds__(256) void split_w_kernel(const float* __restrict__ W)
{
    int i = blockIdx.x * blockDim.x + threadIdx.x;     // quad id, 4096*128
    int n = i >> 7, q = i & 127;
    float4 v = *(const float4*)&W[n * Kdim + (q << 2)];
    float4 lo; ull hi = pack4_hi(v, lo); ull lp = pack4(lo);
    ull* row = (ull*)&g_wa[(size_t)n * KAUG];
    row[q] = hi; row[128 + q] = lp; row[256 + q] = hi;
}

// ---------------- kernel 2: bf16 mma.sync GEMM, occupancy-first config ----
// BM=128 x BN=64 tile, 8 warps in 4x2 grid, warp tile 32x32 (acc=32 regs).
// ~80 regs/thread + 55.3KB smem -> 3 CTAs/SM = 24 warps/SM (was 16).
// 2-stage cp.async (R12 proved depth neutral), one __syncthreads per iter.
#define BM 128
#define BN 64
#define BK2 64
#define NKT2 (KAUG/BK2)      // 24
#define TSTR2 144            // 128B data + 16B pad: conflict-free ldmatrix
#define ATILE3 (BM*TSTR2)    // 18432 B  (A tile)
#define BTILE3 (BN*TSTR2)    // 9216 B   (B tile)
#define STAGE3 (ATILE3+BTILE3) // 27648 B
#define SMEM_GEMM (2*STAGE3)   // 55296 B

__global__ __launch_bounds__(256, 3) void gemm_mma_kernel(const float* __restrict__ bias)
{
    extern __shared__ __align__(16) char sm_dyn[];
    const uint32_t sbase = smem_u32(sm_dyn);
    const int tid = threadIdx.x;
    const int w = tid >> 5, l = tid & 31;
    const int wm = w & 3, wn = w >> 2;             // 4x2 warp grid, warp tile 32x32
    const int m0 = blockIdx.y * BM, n0 = blockIdx.x * BN;

    float acc[2][4][4];
    #pragma unroll
    for (int mt = 0; mt < 2; mt++)
        #pragma unroll
        for (int nt = 0; nt < 4; nt++)
            #pragma unroll
            for (int j = 0; j < 4; j++) acc[mt][nt][j] = 0.0f;

    const int lr = l & 15, lh = l >> 4;
    uint32_t aoff[2], boff[2];
    #pragma unroll
    for (int mt = 0; mt < 2; mt++) aoff[mt] = (uint32_t)((wm*32 + mt*16 + lr) * TSTR2 + lh*16);
    #pragma unroll
    for (int np = 0; np < 2; np++) boff[np] = (uint32_t)((wn*32 + np*16 + lr) * TSTR2 + lh*16);

    // incremental global pointers: thread's chunk = row (tid>>3), kc (tid&7)
    // j-step (+32 rows): global +32*KAUG*2 = 98304 B ; smem +32*TSTR2 = 4608 B
    const int trow = tid >> 3, tkc = tid & 7;
    const char* gA = (const char*)g_xa + ((size_t)(m0 + trow) * KAUG + tkc * 8) * 2;
    const char* gB = (const char*)g_wa + ((size_t)(n0 + trow) * KAUG + tkc * 8) * 2;
    const uint32_t so = (uint32_t)(trow * TSTR2 + tkc * 16);

    auto load_stage = [&](int buf) {
        const uint32_t sA = sbase + (uint32_t)(buf * STAGE3) + so;
        const uint32_t sB = sA + ATILE3;
        #pragma unroll
        for (int j = 0; j < 4; j++) cp16(sA + j * 4608u, gA + j * 98304);  // 128 A rows
        #pragma unroll
        for (int j = 0; j < 2; j++) cp16(sB + j * 4608u, gB + j * 98304);  // 64 B rows
        asm volatile("cp.async.commit_group;" ::: "memory");
        gA += 128;  // advance one BK2 stage (64 bf16)
        gB += 128;
    };

    load_stage(0);

    for (int kt = 0; kt < NKT2; kt++) {
        const int buf = kt & 1;
        asm volatile("cp.async.wait_group 0;" ::: "memory");
        __syncthreads();   // stage kt visible; all warps done computing kt-1
        if (kt + 1 < NKT2) load_stage(buf ^ 1);   // overlaps compute below

        const uint32_t sA = sbase + (uint32_t)(buf * STAGE3);
        const uint32_t sB = sA + ATILE3;
        #pragma unroll
        for (int kk = 0; kk < 4; kk++) {           // four k16 steps per BK=64
            uint32_t a[2][4], b[2][4];
            #pragma unroll
            for (int mt = 0; mt < 2; mt++) LDSM4(a[mt], sA + aoff[mt] + kk*32);
            #pragma unroll
            for (int np = 0; np < 2; np++) LDSM4(b[np], sB + boff[np] + kk*32);
            #pragma unroll
            for (int mt = 0; mt < 2; mt++)
                #pragma unroll
                for (int np = 0; np < 2; np++) {
                    MMA16816(acc[mt][np*2],     a[mt], b[np][0], b[np][2]);
                    MMA16816(acc[mt][np*2 + 1], a[mt], b[np][1], b[np][3]);
                }
        }
    }

    // epilogue: bias + stable sigmoid, write g_pop
    #pragma unroll
    for (int mt = 0; mt < 2; mt++) {
        int row = m0 + wm*32 + mt*16 + (l >> 2);
        #pragma unroll
        for (int nt = 0; nt < 4; nt++) {
            int col = n0 + wn*32 + nt*8 + 2*(l & 3);
            float2 bb = *(const float2*)&bias[col];
            float2 o0, o1;
            o0.x = sigf(acc[mt][nt][0] + bb.x);
            o0.y = sigf(acc[mt][nt][1] + bb.y);
            o1.x = sigf(acc[mt][nt][2] + bb.x);
            o1.y = sigf(acc[mt][nt][3] + bb.y);
            *(float2*)&g_pop[(size_t)row * Ecols + col] = o0;
            *(float2*)&g_pop[(size_t)(row + 8) * Ecols + col] = o1;
        }
    }
}

// ---------------- kernel 3: fused streaming combine (t-quad) --------------
__global__ __launch_bounds__(256) void fuse_kernel(
    const float* __restrict__ freq,
    const float* __restrict__ rrate,
    const float* __restrict__ rpop,
    float* __restrict__ out)
{
    int idx = blockIdx.x * blockDim.x + threadIdx.x;   // [B, 4, S, D] linear
    int d  = idx & (Dd - 1);
    int s  = (idx >> 9) & (Ss - 1);
    int th = (idx >> 17) & 3;        // t quarter: t = th + 4*j
    int b  = idx >> 19;
    int bsd = (b * Ss + s) * Dd + d;
    int i0 = ((b * Tt + th) * Ss + s) * Dd + d;
    const int TS = 4 * Ss * Dd;      // t-step of 4 in elements

    float w0 = g_w[0], w1 = g_w[1], w2 = g_w[2], w3 = g_w[3];

    float rate  = g_rate[bsd];
    int   st    = g_st[bsd];
    float phase = g_phase[bsd];
    float fd    = freq[d];

    const float4* pr4 = (const float4*)g_pop + (size_t)bsd * 2;
    float4 p0 = pr4[0], p1 = pr4[1];

    // issue all rand_pop + rand_rate loads up front (MLP)
    float4 q0[4], q1[4];
    float rr[4];
    #pragma unroll
    for (int j = 0; j < 4; j++) {
        const float4* rp4 = (const float4*)rpop + (size_t)(i0 + j * TS) * 2;
        q0[j] = rp4[0];
        q1[j] = rp4[1];
        rr[j] = rrate[i0 + j * TS];
    }

    const float tstep = 6.2831855f / 15.0f;
    #pragma unroll
    for (int j = 0; j < 4; j++) {
        int t = th + 4 * j;
        int cnt = (q0[j].x < p0.x) + (q0[j].y < p0.y) + (q0[j].z < p0.z) + (q0[j].w < p0.w)
                + (q1[j].x < p1.x) + (q1[j].y < p1.y) + (q1[j].z < p1.z) + (q1[j].w < p1.w);
        float wave = sinf(fd * ((float)t * tstep) + phase);
        float o = w0 * ((rr[j] < rate) ? 1.0f : 0.0f)
                + w1 * ((t == st) ? 1.0f : 0.0f)
                + w2 * ((float)cnt * 0.125f)
                + w3 * ((wave > 0.5f) ? 1.0f : 0.0f);
        out[i0 + j * TS] = o;
    }
}

// ---------------- launch ---------------------------------------------------
extern "C" void kernel_launch(void* const* d_in, const int* in_sizes, int n_in,
                              void* d_out, int out_size)
{
    const float* x     = (const float*)d_in[0];  // [B,S,D]
    const float* freq  = (const float*)d_in[1];  // [D]
    const float* pw    = (const float*)d_in[2];  // [D*N, D]
    const float* pb    = (const float*)d_in[3];  // [D*N]
    const float* ew    = (const float*)d_in[4];  // [4]
    const float* noise = (const float*)d_in[5];  // [B,S,D]
    const float* rr    = (const float*)d_in[6];  // [B,T,S,D]
    const float* rp    = (const float*)d_in[7];  // [B,T,S,D,N]
    float* out = (float*)d_out;                  // [B,T,S,D]

    cudaFuncSetAttribute(gemm_mma_kernel,
                         cudaFuncAttributeMaxDynamicSharedMemorySize, SMEM_GEMM);

    prep_kernel<<<(Bb*Ss*Dd/4) / 256, 256>>>(x, noise, ew);
    split_w_kernel<<<(Ecols*Kdim/4) / 256, 256>>>(pw);
    gemm_mma_kernel<<<dim3(Ecols / BN, Mrows / BM), 256, SMEM_GEMM>>>(pb);
    fuse_kernel<<<(Bb*(Tt/4)*Ss*Dd) / 256, 256>>>(freq, rr, rp, out);
}

// round 16
// speedup vs baseline: 1.3504x; 1.0127x over previous
#include <cuda_runtime.h>
#include <cuda_bf16.h>
#include <math.h>
#include <stdint.h>

// Problem dims
#define Bb 4
#define Tt 16
#define Ss 256
#define Dd 512
#define Nn 8
#define Ecols (Dd*Nn)     // 4096
#define Mrows (Bb*Ss)     // 1024
#define Kdim  Dd          // 512

typedef unsigned long long ull;

// ---------------- scratch (no allocation allowed -> __device__ globals) ----
__device__ __align__(16) float g_pop[Mrows * Ecols];  // sigmoid(pop response) [m,e] (16.8 MB)
__device__ __align__(16) float g_rate[Bb*Ss*Dd];
__device__ __align__(16) float g_phase[Bb*Ss*Dd];
__device__ __align__(16) int   g_st[Bb*Ss*Dd];
__device__ float g_w[4];
// split-bf16 operands, layout per row: [hi (512 bf16) | lo (512 bf16)] = 2KB/row
__device__ __align__(16) __nv_bfloat16 g_xa[Mrows * 2 * Kdim];   // 2 MB
__device__ __align__(16) __nv_bfloat16 g_wa[Ecols * 2 * Kdim];   // 8.4 MB

// ---------------- helpers ----------------
__device__ __forceinline__ float sigf(float x) {
    if (x >= 0.0f) { return 1.0f / (1.0f + expf(-x)); }
    float z = expf(x);
    return z / (1.0f + z);
}

__device__ __forceinline__ uint32_t smem_u32(const void* p) {
    uint32_t a;
    asm("{ .reg .u64 t; cvta.to.shared.u64 t, %1; cvt.u32.u64 %0, t; }" : "=r"(a) : "l"(p));
    return a;
}

__device__ __forceinline__ void cp16(uint32_t s, const void* g) {
    asm volatile("cp.async.cg.shared.global [%0], [%1], 16;" :: "r"(s), "l"(g) : "memory");
}

#define LDSM4(r, addr) \
    asm volatile("ldmatrix.sync.aligned.m8n8.x4.shared.b16 {%0,%1,%2,%3}, [%4];" \
        : "=r"((r)[0]), "=r"((r)[1]), "=r"((r)[2]), "=r"((r)[3]) : "r"(addr))

#define MMA16816(d, a, b0, b1) \
    asm volatile("mma.sync.aligned.m16n8k16.row.col.f32.bf16.bf16.f32 " \
        "{%0,%1,%2,%3}, {%4,%5,%6,%7}, {%8,%9}, {%0,%1,%2,%3};" \
        : "+f"((d)[0]), "+f"((d)[1]), "+f"((d)[2]), "+f"((d)[3]) \
        : "r"((a)[0]), "r"((a)[1]), "r"((a)[2]), "r"((a)[3]), "r"(b0), "r"(b1))

__device__ __forceinline__ ull pack4_hi(float4 v, float4& lo) {
    __nv_bfloat16 h0 = __float2bfloat16_rn(v.x);
    __nv_bfloat16 h1 = __float2bfloat16_rn(v.y);
    __nv_bfloat16 h2 = __float2bfloat16_rn(v.z);
    __nv_bfloat16 h3 = __float2bfloat16_rn(v.w);
    lo.x = v.x - __bfloat162float(h0);
    lo.y = v.y - __bfloat162float(h1);
    lo.z = v.z - __bfloat162float(h2);
    lo.w = v.w - __bfloat162float(h3);
    __nv_bfloat162 p0; p0.x = h0; p0.y = h1;
    __nv_bfloat162 p1; p1.x = h2; p1.y = h3;
    uint32_t u0 = *(uint32_t*)&p0, u1 = *(uint32_t*)&p1;
    return (ull)u0 | ((ull)u1 << 32);
}
__device__ __forceinline__ ull pack4(float4 v) {
    __nv_bfloat162 p0; p0.x = __float2bfloat16_rn(v.x); p0.y = __float2bfloat16_rn(v.y);
    __nv_bfloat162 p1; p1.x = __float2bfloat16_rn(v.z); p1.y = __float2bfloat16_rn(v.w);
    uint32_t u0 = *(uint32_t*)&p0, u1 = *(uint32_t*)&p1;
    return (ull)u0 | ((ull)u1 << 32);
}

// ---------------- kernel 1: prep (vectorized x4) + split_x + softmax ------
__global__ __launch_bounds__(256) void prep_kernel(
    const float* __restrict__ x,
    const float* __restrict__ noise,
    const float* __restrict__ ew)
{
    int i = blockIdx.x * blockDim.x + threadIdx.x;     // quad id, 131072 total
    float4 xv = *(const float4*)&x[i * 4];
    float4 nv = *(const float4*)&noise[i * 4];

    float s0 = sigf(xv.x), s1 = sigf(xv.y), s2 = sigf(xv.z), s3 = sigf(xv.w);

    float4 rv;
    rv.x = fminf(fmaxf(s0 * 0.9f + 0.05f + nv.x * 0.1f, 0.0f), 1.0f);
    rv.y = fminf(fmaxf(s1 * 0.9f + 0.05f + nv.y * 0.1f, 0.0f), 1.0f);
    rv.z = fminf(fmaxf(s2 * 0.9f + 0.05f + nv.z * 0.1f, 0.0f), 1.0f);
    rv.w = fminf(fmaxf(s3 * 0.9f + 0.05f + nv.w * 0.1f, 0.0f), 1.0f);
    *(float4*)&g_rate[i * 4] = rv;

    int4 st;
    st.x = (int)(s0 * 15.0f); st.y = (int)(s1 * 15.0f);
    st.z = (int)(s2 * 15.0f); st.w = (int)(s3 * 15.0f);
    *(int4*)&g_st[i * 4] = st;

    float4 ph;
    ph.x = s0 * 6.2831855f; ph.y = s1 * 6.2831855f;
    ph.z = s2 * 6.2831855f; ph.w = s3 * 6.2831855f;
    *(float4*)&g_phase[i * 4] = ph;

    // X split: row m, [hi|lo] halves of 512 bf16 each = 128 ull each
    int m = i >> 7, q = i & 127;
    float4 lo; ull hi = pack4_hi(xv, lo); ull lp = pack4(lo);
    ull* row = (ull*)&g_xa[(size_t)m * 2 * Kdim];
    row[q] = hi; row[128 + q] = lp;

    if (i == 0) {
        float m2 = fmaxf(fmaxf(ew[0], ew[1]), fmaxf(ew[2], ew[3]));
        float e0 = expf(ew[0]-m2), e1 = expf(ew[1]-m2), e2 = expf(ew[2]-m2), e3 = expf(ew[3]-m2);
        float s = e0 + e1 + e2 + e3;
        g_w[0] = e0/s; g_w[1] = e1/s; g_w[2] = e2/s; g_w[3] = e3/s;
    }
}

// ---------------- kernel 1b: split W -> [hi|lo] ---------------------------
__global__ __launch_bounds__(256) void split_w_kernel(const float* __restrict__ W)
{
    int i = blockIdx.x * blockDim.x + threadIdx.x;     // quad id, 4096*128
    int n = i >> 7, q = i & 127;
    float4 v = *(const float4*)&W[n * Kdim + (q << 2)];
    float4 lo; ull hi = pack4_hi(v, lo); ull lp = pack4(lo);
    ull* row = (ull*)&g_wa[(size_t)n * 2 * Kdim];
    row[q] = hi; row[128 + q] = lp;
}

// ---------------- kernel 2: low-traffic 3-product split GEMM --------------
// g_pop[m,e] = sigmoid( Xhi.Whi + Xhi.Wlo + Xlo.Whi + bias[e] )
// Per 32-K stage: load Ahi/Alo/Bhi/Blo sub-tiles (32KB) and run all 3
// products from the same SMEM -> L2 traffic 131MB (was 197), MMA:LDSM 4:1.
// 256 thr, 8 warps 4x2 (warp tile 32x64), 2-stage cp.async, 2 CTAs/SM,
// 256 CTAs = one full wave.
#define BM 128
#define BN 128
#define BK 32
#define NIT (Kdim/BK)        // 16
#define SSTR 80              // 64B data + 16B pad: 20-word stride -> conflict-free ldmatrix
#define SUBT (128*SSTR)      // 10240 B per sub-tile
#define STAGE (4*SUBT)       // 40960 B : [Ahi, Alo, Bhi, Blo]
#define SMEM_GEMM (2*STAGE)  // 81920 B

__global__ __launch_bounds__(256, 2) void gemm_mma_kernel(const float* __restrict__ bias)
{
    extern __shared__ __align__(16) char sm_dyn[];
    const uint32_t sbase = smem_u32(sm_dyn);
    const int tid = threadIdx.x;
    const int w = tid >> 5, l = tid & 31;
    const int wm = w & 3, wn = w >> 2;             // 4x2 warp grid, warp tile 32x64
    const int m0 = blockIdx.y * BM, n0 = blockIdx.x * BN;

    float acc[2][8][4];
    #pragma unroll
    for (int mt = 0; mt < 2; mt++)
        #pragma unroll
        for (int nt = 0; nt < 8; nt++)
            #pragma unroll
            for (int j = 0; j < 4; j++) acc[mt][nt][j] = 0.0f;

    const int lr = l & 15, lh = l >> 4;
    uint32_t aoff[2], boff[4];
    #pragma unroll
    for (int mt = 0; mt < 2; mt++) aoff[mt] = (uint32_t)((wm*32 + mt*16 + lr) * SSTR + lh*16);
    #pragma unroll
    for (int np = 0; np < 4; np++) boff[np] = (uint32_t)((wn*64 + np*16 + lr) * SSTR + lh*16);

    // loader: thread covers rows r1=tid>>2 and r2=r1+64, 16B chunk kc=tid&3,
    // for each of the 4 sub-tiles (hi/lo derived by +1024B within a row).
    const int r1 = tid >> 2, kc = tid & 3;
    const char* gx1 = (const char*)g_xa + (size_t)(m0 + r1)      * 2048 + kc * 16;
    const char* gx2 = (const char*)g_xa + (size_t)(m0 + r1 + 64) * 2048 + kc * 16;
    const char* gw1 = (const char*)g_wa + (size_t)(n0 + r1)      * 2048 + kc * 16;
    const char* gw2 = (const char*)g_wa + (size_t)(n0 + r1 + 64) * 2048 + kc * 16;
    const uint32_t so1 = (uint32_t)(r1 * SSTR + kc * 16);
    const uint32_t so2 = so1 + 64u * SSTR;

    auto load_stage = [&](int buf) {
        const uint32_t bs = sbase + (uint32_t)(buf * STAGE);
        cp16(bs + so1,            gx1);          // Ahi
        cp16(bs + so2,            gx2);
        cp16(bs + SUBT + so1,     gx1 + 1024);   // Alo
        cp16(bs + SUBT + so2,     gx2 + 1024);
        cp16(bs + 2*SUBT + so1,   gw1);          // Bhi
        cp16(bs + 2*SUBT + so2,   gw2);
        cp16(bs + 3*SUBT + so1,   gw1 + 1024);   // Blo
        cp16(bs + 3*SUBT + so2,   gw2 + 1024);
        asm volatile("cp.async.commit_group;" ::: "memory");
        gx1 += 64; gx2 += 64; gw1 += 64; gw2 += 64;   // advance 32 bf16
    };

    load_stage(0);

    for (int kt = 0; kt < NIT; kt++) {
        const int buf = kt & 1;
        asm volatile("cp.async.wait_group 0;" ::: "memory");
        __syncthreads();
        if (kt + 1 < NIT) load_stage(buf ^ 1);   // overlaps compute below

        const uint32_t sAhi = sbase + (uint32_t)(buf * STAGE);
        const uint32_t sAlo = sAhi + SUBT;
        const uint32_t sBhi = sAhi + 2*SUBT;
        const uint32_t sBlo = sAhi + 3*SUBT;
        #pragma unroll
        for (int kk = 0; kk < 2; kk++) {           // two k16 steps per BK=32
            uint32_t ah[2][4], al[2][4];
            #pragma unroll
            for (int mt = 0; mt < 2; mt++) {
                LDSM4(ah[mt], sAhi + aoff[mt] + kk*32);
                LDSM4(al[mt], sAlo + aoff[mt] + kk*32);
            }
            #pragma unroll
            for (int np = 0; np < 4; np++) {
                uint32_t bh[4], bl[4];
                LDSM4(bh, sBhi + boff[np] + kk*32);
                LDSM4(bl, sBlo + boff[np] + kk*32);
                #pragma unroll
                for (int mt = 0; mt < 2; mt++) {
                    MMA16816(acc[mt][np*2],     ah[mt], bh[0], bh[2]);   // hh
                    MMA16816(acc[mt][np*2 + 1], ah[mt], bh[1], bh[3]);
                    MMA16816(acc[mt][np*2],     ah[mt], bl[0], bl[2]);   // hl
                    MMA16816(acc[mt][np*2 + 1], ah[mt], bl[1], bl[3]);
                    MMA16816(acc[mt][np*2],     al[mt], bh[0], bh[2]);   // lh
                    MMA16816(acc[mt][np*2 + 1], al[mt], bh[1], bh[3]);
                }
            }
        }
    }

    // epilogue: bias + stable sigmoid, write g_pop
    #pragma unroll
    for (int mt = 0; mt < 2; mt++) {
        int row = m0 + wm*32 + mt*16 + (l >> 2);
        #pragma unroll
        for (int nt = 0; nt < 8; nt++) {
            int col = n0 + wn*64 + nt*8 + 2*(l & 3);
            float2 bb = *(const float2*)&bias[col];
            float2 o0, o1;
            o0.x = sigf(acc[mt][nt][0] + bb.x);
            o0.y = sigf(acc[mt][nt][1] + bb.y);
            o1.x = sigf(acc[mt][nt][2] + bb.x);
            o1.y = sigf(acc[mt][nt][3] + bb.y);
            *(float2*)&g_pop[(size_t)row * Ecols + col] = o0;
            *(float2*)&g_pop[(size_t)(row + 8) * Ecols + col] = o1;
        }
    }
}

// ---------------- kernel 3: fused streaming combine (t-quad) --------------
__global__ __launch_bounds__(256) void fuse_kernel(
    const float* __restrict__ freq,
    const float* __restrict__ rrate,
    const float* __restrict__ rpop,
    float* __restrict__ out)
{
    int idx = blockIdx.x * blockDim.x + threadIdx.x;   // [B, 4, S, D] linear
    int d  = idx & (Dd - 1);
    int s  = (idx >> 9) & (Ss - 1);
    int th = (idx >> 17) & 3;        // t quarter: t = th + 4*j
    int b  = idx >> 19;
    int bsd = (b * Ss + s) * Dd + d;
    int i0 = ((b * Tt + th) * Ss + s) * Dd + d;
    const int TS = 4 * Ss * Dd;      // t-step of 4 in elements

    float w0 = g_w[0], w1 = g_w[1], w2 = g_w[2], w3 = g_w[3];

    float rate  = g_rate[bsd];
    int   st    = g_st[bsd];
    float phase = g_phase[bsd];
    float fd    = freq[d];

    const float4* pr4 = (const float4*)g_pop + (size_t)bsd * 2;
    float4 p0 = pr4[0], p1 = pr4[1];

    // issue all rand_pop + rand_rate loads up front (MLP)
    float4 q0[4], q1[4];
    float rr[4];
    #pragma unroll
    for (int j = 0; j < 4; j++) {
        const float4* rp4 = (const float4*)rpop + (size_t)(i0 + j * TS) * 2;
        q0[j] = rp4[0];
        q1[j] = rp4[1];
        rr[j] = rrate[i0 + j * TS];
    }

    const float tstep = 6.2831855f / 15.0f;
    #pragma unroll
    for (int j = 0; j < 4; j++) {
        int t = th + 4 * j;
        int cnt = (q0[j].x < p0.x) + (q0[j].y < p0.y) + (q0[j].z < p0.z) + (q0[j].w < p0.w)
                + (q1[j].x < p1.x) + (q1[j].y < p1.y) + (q1[j].z < p1.z) + (q1[j].w < p1.w);
        float wave = sinf(fd * ((float)t * tstep) + phase);
        float o = w0 * ((rr[j] < rate) ? 1.0f : 0.0f)
                + w1 * ((t == st) ? 1.0f : 0.0f)
                + w2 * ((float)cnt * 0.125f)
                + w3 * ((wave > 0.5f) ? 1.0f : 0.0f);
        out[i0 + j * TS] = o;
    }
}

// ---------------- launch ---------------------------------------------------
extern "C" void kernel_launch(void* const* d_in, const int* in_sizes, int n_in,
                              void* d_out, int out_size)
{
    const float* x     = (const float*)d_in[0];  // [B,S,D]
    const float* freq  = (const float*)d_in[1];  // [D]
    const float* pw    = (const float*)d_in[2];  // [D*N, D]
    const float* pb    = (const float*)d_in[3];  // [D*N]
    const float* ew    = (const float*)d_in[4];  // [4]
    const float* noise = (const float*)d_in[5];  // [B,S,D]
    const float* rr    = (const float*)d_in[6];  // [B,T,S,D]
    const float* rp    = (const float*)d_in[7];  // [B,T,S,D,N]
    float* out = (float*)d_out;                  // [B,T,S,D]

    cudaFuncSetAttribute(gemm_mma_kernel,
                         cudaFuncAttributeMaxDynamicSharedMemorySize, SMEM_GEMM);

    prep_kernel<<<(Bb*Ss*Dd/4) / 256, 256>>>(x, noise, ew);
    split_w_kernel<<<(Ecols*Kdim/4) / 256, 256>>>(pw);
    gemm_mma_kernel<<<dim3(Ecols / BN, Mrows / BM), 256, SMEM_GEMM>>>(pb);
    fuse_kernel<<<(Bb*(Tt/4)*Ss*Dd) / 256, 256>>>(freq, rr, rp, out);
}